// round 14
// baseline (speedup 1.0000x reference)
#include <cuda_runtime.h>
#include <cuda_fp16.h>
#include <cstdint>

// Problem constants
#define BATCH 16
#define CIN   256
#define HWN   4096          // 64*64
#define C3    768           // 3*TOTAL
#define CATT  512           // 2*TOTAL
#define PWG   96

// ---------------------------------------------------------------------------
// Scratch (static device memory)
// ---------------------------------------------------------------------------
__device__ float g_qkv[BATCH * C3 * HWN];               // 201 MB
__device__ float g_agg[BATCH * C3 * HWN];               // 201 MB
__device__ __half g_attT[BATCH * HWN * CATT];           // 67 MB (fp16, single)
__device__ __half g_wqkv_hi[C3 * CIN];
__device__ __half g_wqkv_lo[C3 * CIN];
__device__ __half g_wproj_hi[256 * CATT];
__device__ __half g_wproj_lo[256 * CATT];

// ---------------------------------------------------------------------------
// Helpers
// ---------------------------------------------------------------------------
__device__ __forceinline__ uint32_t smem_u32(const void* p) {
    uint32_t a;
    asm("{ .reg .u64 t; cvta.to.shared.u64 t, %1; cvt.u32.u64 %0, t; }" : "=r"(a) : "l"(p));
    return a;
}
__device__ __forceinline__ void ldmx4(uint32_t* r, uint32_t addr) {
    asm volatile("ldmatrix.sync.aligned.m8n8.x4.shared.b16 {%0,%1,%2,%3}, [%4];"
                 : "=r"(r[0]), "=r"(r[1]), "=r"(r[2]), "=r"(r[3]) : "r"(addr));
}
__device__ __forceinline__ void ldmx2(uint32_t* r, uint32_t addr) {
    asm volatile("ldmatrix.sync.aligned.m8n8.x2.shared.b16 {%0,%1}, [%2];"
                 : "=r"(r[0]), "=r"(r[1]) : "r"(addr));
}
__device__ __forceinline__ void mma_f16(float* d, const uint32_t* a, const uint32_t* b) {
    asm volatile(
        "mma.sync.aligned.m16n8k16.row.col.f32.f16.f16.f32 "
        "{%0,%1,%2,%3}, {%4,%5,%6,%7}, {%8,%9}, {%0,%1,%2,%3};"
        : "+f"(d[0]), "+f"(d[1]), "+f"(d[2]), "+f"(d[3])
        : "r"(a[0]), "r"(a[1]), "r"(a[2]), "r"(a[3]), "r"(b[0]), "r"(b[1]));
}

// ---------------------------------------------------------------------------
// fp16 weight split
// ---------------------------------------------------------------------------
__global__ void split_f16(const float* __restrict__ src,
                          __half* __restrict__ hi, __half* __restrict__ lo, int n) {
    int i = blockIdx.x * 256 + threadIdx.x;
    if (i < n) {
        float v = src[i];
        __half h = __float2half_rn(v);
        hi[i] = h;
        lo[i] = __float2half_rn(v - __half2float(h));
    }
}

// ---------------------------------------------------------------------------
// qkv GEMM: fp16 3-term split, fused x transpose+split in the B loader.
// ---------------------------------------------------------------------------
#define BK  32
#define LDS 40

__global__ __launch_bounds__(256, 2) void gemm_qkv(
    const __half* __restrict__ Ahi, const __half* __restrict__ Alo,
    const float* __restrict__ Xg, float* __restrict__ Cg, int M, int K) {
    __shared__ __half As_hi[128 * LDS];
    __shared__ __half As_lo[128 * LDS];
    __shared__ __half Bs_hi[128 * LDS];
    __shared__ __half Bs_lo[128 * LDS];

    const int tid = threadIdx.x;
    const int wid = tid >> 5;
    const int lane = tid & 31;

    const int b = blockIdx.z;
    const int m0 = blockIdx.y * 128;
    const int n0 = blockIdx.x * 128;

    const float* Xb = Xg + (size_t)b * CIN * HWN;

    const int wm = (wid >> 2) * 64;
    const int wn = (wid & 3) * 32;

    const int ar = lane & 15, ac = (lane >> 4) << 3;
    const int br = lane & 7,  bc = ((lane >> 3) & 1) << 3;

    const int pair = tid & 15;        // channel pair
    const int pgrp = tid >> 4;        // pixel group (8 pixels)

    float acc[4][4][4];
#pragma unroll
    for (int mt = 0; mt < 4; mt++)
#pragma unroll
        for (int nt = 0; nt < 4; nt++)
#pragma unroll
            for (int r = 0; r < 4; r++) acc[mt][nt][r] = 0.f;

    for (int kc = 0; kc < K; kc += BK) {
#pragma unroll
        for (int i = 0; i < 2; i++) {
            int u = tid + 256 * i;
            int row = u >> 2;
            int cu = (u & 3) << 3;
            size_t sa = (size_t)(m0 + row) * K + kc + cu;
            *(uint4*)&As_hi[row * LDS + cu] = *(const uint4*)(Ahi + sa);
            *(uint4*)&As_lo[row * LDS + cu] = *(const uint4*)(Alo + sa);
        }
        {
            const float* x0 = Xb + (size_t)(kc + 2 * pair) * HWN + n0 + pgrp * 8;
            const float* x1 = x0 + HWN;
            float4 a0 = *(const float4*)(x0);
            float4 a1 = *(const float4*)(x0 + 4);
            float4 c0 = *(const float4*)(x1);
            float4 c1 = *(const float4*)(x1 + 4);
            float va[8] = {a0.x, a0.y, a0.z, a0.w, a1.x, a1.y, a1.z, a1.w};
            float vb[8] = {c0.x, c0.y, c0.z, c0.w, c1.x, c1.y, c1.z, c1.w};
#pragma unroll
            for (int i = 0; i < 8; i++) {
                __half h0 = __float2half_rn(va[i]);
                __half l0 = __float2half_rn(va[i] - __half2float(h0));
                __half h1 = __float2half_rn(vb[i]);
                __half l1 = __float2half_rn(vb[i] - __half2float(h1));
                int off = (pgrp * 8 + i) * LDS + 2 * pair;
                *(__half2*)&Bs_hi[off] = __halves2half2(h0, h1);
                *(__half2*)&Bs_lo[off] = __halves2half2(l0, l1);
            }
        }
        __syncthreads();

#pragma unroll
        for (int kk = 0; kk < BK; kk += 16) {
            uint32_t ah[4][4], bhf[4][2];
#pragma unroll
            for (int mt = 0; mt < 4; mt++)
                ldmx4(ah[mt], smem_u32(&As_hi[(wm + mt * 16 + ar) * LDS + kk + ac]));
#pragma unroll
            for (int nt = 0; nt < 4; nt++)
                ldmx2(bhf[nt], smem_u32(&Bs_hi[(wn + nt * 8 + br) * LDS + kk + bc]));
#pragma unroll
            for (int mt = 0; mt < 4; mt++)
#pragma unroll
                for (int nt = 0; nt < 4; nt++)
                    mma_f16(acc[mt][nt], ah[mt], bhf[nt]);

            uint32_t al[4][4];
#pragma unroll
            for (int mt = 0; mt < 4; mt++)
                ldmx4(al[mt], smem_u32(&As_lo[(wm + mt * 16 + ar) * LDS + kk + ac]));
#pragma unroll
            for (int mt = 0; mt < 4; mt++)
#pragma unroll
                for (int nt = 0; nt < 4; nt++)
                    mma_f16(acc[mt][nt], al[mt], bhf[nt]);

            uint32_t blf[4][2];
#pragma unroll
            for (int nt = 0; nt < 4; nt++)
                ldmx2(blf[nt], smem_u32(&Bs_lo[(wn + nt * 8 + br) * LDS + kk + bc]));
#pragma unroll
            for (int mt = 0; mt < 4; mt++)
#pragma unroll
                for (int nt = 0; nt < 4; nt++)
                    mma_f16(acc[mt][nt], ah[mt], blf[nt]);
        }
        __syncthreads();
    }

#pragma unroll
    for (int mt = 0; mt < 4; mt++) {
        const int row0 = m0 + wm + mt * 16 + (lane >> 2);
        const int row1 = row0 + 8;
        float* c0p = Cg + ((size_t)b * M + row0) * HWN + n0 + wn;
        float* c1p = Cg + ((size_t)b * M + row1) * HWN + n0 + wn;
        const int coff = ((lane & 3) << 1);
#pragma unroll
        for (int nt = 0; nt < 4; nt++) {
            *(float2*)(c0p + nt * 8 + coff) = make_float2(acc[mt][nt][0], acc[mt][nt][1]);
            *(float2*)(c1p + nt * 8 + coff) = make_float2(acc[mt][nt][2], acc[mt][nt][3]);
        }
    }
}

// ---------------------------------------------------------------------------
// proj GEMM: fp16 2-term split + BN epilogue (proven R13 version).
// ---------------------------------------------------------------------------
__global__ __launch_bounds__(256, 2) void gemm_proj(
    const __half* __restrict__ Ahi, const __half* __restrict__ Alo,
    const __half* __restrict__ Bg, float* __restrict__ Cg, int M, int K,
    const float* __restrict__ gamma, const float* __restrict__ beta,
    const float* __restrict__ mean, const float* __restrict__ var) {
    __shared__ __half As_hi[128 * LDS];
    __shared__ __half As_lo[128 * LDS];
    __shared__ __half Bs[128 * LDS];

    const int tid = threadIdx.x;
    const int wid = tid >> 5;
    const int lane = tid & 31;

    const int b = blockIdx.z;
    const int m0 = blockIdx.y * 128;
    const int n0 = blockIdx.x * 128;

    const __half* Bb = Bg + (size_t)b * HWN * K;

    const int wm = (wid >> 2) * 64;
    const int wn = (wid & 3) * 32;

    const int ar = lane & 15, ac = (lane >> 4) << 3;
    const int br = lane & 7,  bc = ((lane >> 3) & 1) << 3;

    float acc[4][4][4];
#pragma unroll
    for (int mt = 0; mt < 4; mt++)
#pragma unroll
        for (int nt = 0; nt < 4; nt++)
#pragma unroll
            for (int r = 0; r < 4; r++) acc[mt][nt][r] = 0.f;

    for (int kc = 0; kc < K; kc += BK) {
#pragma unroll
        for (int i = 0; i < 2; i++) {
            int u = tid + 256 * i;
            int row = u >> 2;
            int cu = (u & 3) << 3;
            size_t sa = (size_t)(m0 + row) * K + kc + cu;
            *(uint4*)&As_hi[row * LDS + cu] = *(const uint4*)(Ahi + sa);
            *(uint4*)&As_lo[row * LDS + cu] = *(const uint4*)(Alo + sa);
            size_t sb = (size_t)(n0 + row) * K + kc + cu;
            *(uint4*)&Bs[row * LDS + cu] = *(const uint4*)(Bb + sb);
        }
        __syncthreads();

#pragma unroll
        for (int kk = 0; kk < BK; kk += 16) {
            uint32_t ah[4][4], bf[4][2];
#pragma unroll
            for (int mt = 0; mt < 4; mt++)
                ldmx4(ah[mt], smem_u32(&As_hi[(wm + mt * 16 + ar) * LDS + kk + ac]));
#pragma unroll
            for (int nt = 0; nt < 4; nt++)
                ldmx2(bf[nt], smem_u32(&Bs[(wn + nt * 8 + br) * LDS + kk + bc]));
#pragma unroll
            for (int mt = 0; mt < 4; mt++)
#pragma unroll
                for (int nt = 0; nt < 4; nt++)
                    mma_f16(acc[mt][nt], ah[mt], bf[nt]);

            uint32_t al[4][4];
#pragma unroll
            for (int mt = 0; mt < 4; mt++)
                ldmx4(al[mt], smem_u32(&As_lo[(wm + mt * 16 + ar) * LDS + kk + ac]));
#pragma unroll
            for (int mt = 0; mt < 4; mt++)
#pragma unroll
                for (int nt = 0; nt < 4; nt++)
                    mma_f16(acc[mt][nt], al[mt], bf[nt]);
        }
        __syncthreads();
    }

#pragma unroll
    for (int mt = 0; mt < 4; mt++) {
        const int row0 = m0 + wm + mt * 16 + (lane >> 2);
        const int row1 = row0 + 8;
        float iv0 = gamma[row0] * rsqrtf(var[row0] + 1e-5f);
        float s0 = iv0, o0 = beta[row0] - mean[row0] * iv0;
        float iv1 = gamma[row1] * rsqrtf(var[row1] + 1e-5f);
        float s1 = iv1, o1 = beta[row1] - mean[row1] * iv1;
        float* c0p = Cg + ((size_t)b * M + row0) * HWN + n0 + wn;
        float* c1p = Cg + ((size_t)b * M + row1) * HWN + n0 + wn;
        const int coff = ((lane & 3) << 1);
#pragma unroll
        for (int nt = 0; nt < 4; nt++) {
            float2 v0, v1;
            v0.x = acc[mt][nt][0] * s0 + o0;
            v0.y = acc[mt][nt][1] * s0 + o0;
            v1.x = acc[mt][nt][2] * s1 + o1;
            v1.y = acc[mt][nt][3] * s1 + o1;
            *(float2*)(c0p + nt * 8 + coff) = v0;
            *(float2*)(c1p + nt * 8 + coff) = v1;
        }
    }
}

// ---------------------------------------------------------------------------
// FUSED depthwise 5x5 (pad 2) + grouped 1x1 (8-ch groups).
// R14: thread = 4 consecutive x-pixels x 1 row. Conv loads via LDS.128
// (2 per halo row), outputs via STG.128. FMA count unchanged.
// ---------------------------------------------------------------------------
__global__ __launch_bounds__(256) void dwpw(
    const float* __restrict__ qkv, const float* __restrict__ w_dw,
    const float* __restrict__ w_pw, float* __restrict__ agg) {
    const int tile = blockIdx.x;
    const int g = blockIdx.y;
    const int b = blockIdx.z;
    const int ty = (tile >> 1) * 32;
    const int tx = (tile & 1) * 32;

    __shared__ __align__(16) float h[8][36 * 36];
    __shared__ float wd[8][25];
    __shared__ float wp[64];

    const int tid = threadIdx.x;
    if (tid < 64) wp[tid] = w_pw[g * 64 + tid];
    if (tid < 200) {
        int c = tid / 25, t = tid % 25;
        wd[c][t] = w_dw[(g * 8 + c) * 25 + t];
    }

    const float* ip = qkv + ((size_t)b * C3 + (size_t)g * 8) * HWN;
    for (int idx = tid; idx < 8 * 1296; idx += 256) {
        int c = idx / 1296, rem = idx - c * 1296;
        int hy = rem / 36, hx = rem - hy * 36;
        int gy = ty + hy - 2, gx = tx + hx - 2;
        float v = 0.f;
        if ((unsigned)gy < 64u && (unsigned)gx < 64u) v = ip[(size_t)c * HWN + gy * 64 + gx];
        h[c][rem] = v;
    }
    __syncthreads();

    const int xq = (tid & 7) << 2;   // x offset: 0,4,...,28
    const int yy = tid >> 3;         // output row 0..31

    float d[8][4];                   // [channel][x-pixel]
#pragma unroll
    for (int c = 0; c < 8; c++) {
        float o0 = 0.f, o1 = 0.f, o2 = 0.f, o3 = 0.f;
#pragma unroll
        for (int dy = 0; dy < 5; dy++) {
            const float* hp = &h[c][(yy + dy) * 36 + xq];
            float v[8];
            *(float4*)&v[0] = *(const float4*)(hp);
            *(float4*)&v[4] = *(const float4*)(hp + 4);
            const float* w5 = &wd[c][dy * 5];
#pragma unroll
            for (int dx = 0; dx < 5; dx++) {
                float w = w5[dx];
                o0 = fmaf(v[0 + dx], w, o0);
                o1 = fmaf(v[1 + dx], w, o1);
                o2 = fmaf(v[2 + dx], w, o2);
                o3 = fmaf(v[3 + dx], w, o3);
            }
        }
        d[c][0] = o0; d[c][1] = o1; d[c][2] = o2; d[c][3] = o3;
    }

    float* op = agg + ((size_t)b * C3 + (size_t)g * 8) * HWN
                    + (size_t)(ty + yy) * 64 + tx + xq;
#pragma unroll
    for (int o = 0; o < 8; o++) {
        float4 r;
        r.x = 0.f; r.y = 0.f; r.z = 0.f; r.w = 0.f;
#pragma unroll
        for (int c = 0; c < 8; c++) {
            float w = wp[o * 8 + c];
            r.x = fmaf(w, d[c][0], r.x);
            r.y = fmaf(w, d[c][1], r.y);
            r.z = fmaf(w, d[c][2], r.z);
            r.w = fmaf(w, d[c][3], r.w);
        }
        *(float4*)(op + (size_t)o * HWN) = r;
    }
}

// ---------------------------------------------------------------------------
// ReLU linear attention; writes transposed fp16 output attT[b][n][g*8+e].
// ---------------------------------------------------------------------------
__global__ __launch_bounds__(256) void relu_lin_att(
    const float* __restrict__ qkv, const float* __restrict__ agg,
    __half* __restrict__ outp) {
    const int bg = blockIdx.x;
    const int b = bg >> 6;
    const int g = bg & 63;
    const float* base = (g < 32)
        ? qkv + ((size_t)b * C3 + (size_t)g * 24) * HWN
        : agg + ((size_t)b * C3 + (size_t)(g - 32) * 24) * HWN;

    __shared__ float kvs[72];
    const int tid = threadIdx.x;
    const int w = tid >> 5;
    const int lane = tid & 31;

    float kvr[9];
#pragma unroll
    for (int i = 0; i < 9; i++) kvr[i] = 0.f;

    const float* kch = base + (size_t)(8 + w) * HWN;
    for (int n4 = lane * 4; n4 < HWN; n4 += 128) {
        float4 kk = *(const float4*)(kch + n4);
        kk.x = fmaxf(kk.x, 0.f); kk.y = fmaxf(kk.y, 0.f);
        kk.z = fmaxf(kk.z, 0.f); kk.w = fmaxf(kk.w, 0.f);
#pragma unroll
        for (int e = 0; e < 8; e++) {
            float4 vv = *(const float4*)(base + (size_t)(16 + e) * HWN + n4);
            kvr[e] = fmaf(kk.x, vv.x, kvr[e]);
            kvr[e] = fmaf(kk.y, vv.y, kvr[e]);
            kvr[e] = fmaf(kk.z, vv.z, kvr[e]);
            kvr[e] = fmaf(kk.w, vv.w, kvr[e]);
        }
        kvr[8] += kk.x + kk.y + kk.z + kk.w;
    }
#pragma unroll
    for (int i = 0; i < 9; i++) {
        float v = kvr[i];
        v += __shfl_xor_sync(0xffffffffu, v, 16);
        v += __shfl_xor_sync(0xffffffffu, v, 8);
        v += __shfl_xor_sync(0xffffffffu, v, 4);
        v += __shfl_xor_sync(0xffffffffu, v, 2);
        v += __shfl_xor_sync(0xffffffffu, v, 1);
        if (lane == 0) kvs[w * 9 + i] = v;
    }
    __syncthreads();

    for (int n4 = tid * 4; n4 < HWN; n4 += 1024) {
        float4 q4[8];
#pragma unroll
        for (int d0 = 0; d0 < 8; d0++) {
            float4 q = *(const float4*)(base + (size_t)d0 * HWN + n4);
            q.x = fmaxf(q.x, 0.f); q.y = fmaxf(q.y, 0.f);
            q.z = fmaxf(q.z, 0.f); q.w = fmaxf(q.w, 0.f);
            q4[d0] = q;
        }
#pragma unroll
        for (int px = 0; px < 4; px++) {
            float qd[8];
#pragma unroll
            for (int d0 = 0; d0 < 8; d0++)
                qd[d0] = px == 0 ? q4[d0].x : px == 1 ? q4[d0].y : px == 2 ? q4[d0].z : q4[d0].w;
            float den = 0.f;
#pragma unroll
            for (int d0 = 0; d0 < 8; d0++) den = fmaf(qd[d0], kvs[d0 * 9 + 8], den);
            float rden = 1.f / (den + 1e-15f);
            __align__(16) __half o[8];
#pragma unroll
            for (int e = 0; e < 8; e++) {
                float num = 0.f;
#pragma unroll
                for (int d0 = 0; d0 < 8; d0++) num = fmaf(qd[d0], kvs[d0 * 9 + e], num);
                o[e] = __float2half_rn(num * rden);
            }
            size_t idx = ((size_t)b * HWN + n4 + px) * CATT + g * 8;
            *(uint4*)(outp + idx) = *(const uint4*)o;
        }
    }
}

// ---------------------------------------------------------------------------
// Launch
// ---------------------------------------------------------------------------
extern "C" void kernel_launch(void* const* d_in, const int* in_sizes, int n_in,
                              void* d_out, int out_size) {
    const float* x      = (const float*)d_in[0];
    const float* w_qkv  = (const float*)d_in[1];
    const float* w_dw   = (const float*)d_in[2];
    const float* w_pw   = (const float*)d_in[3];
    const float* w_proj = (const float*)d_in[4];
    const float* gamma  = (const float*)d_in[5];
    const float* beta   = (const float*)d_in[6];
    const float* mean   = (const float*)d_in[7];
    const float* var    = (const float*)d_in[8];
    float* out = (float*)d_out;

    float *qkv_s, *agg_s;
    __half *att, *wqh, *wql, *wph, *wpl;
    cudaGetSymbolAddress((void**)&qkv_s, g_qkv);
    cudaGetSymbolAddress((void**)&agg_s, g_agg);
    cudaGetSymbolAddress((void**)&att, g_attT);
    cudaGetSymbolAddress((void**)&wqh, g_wqkv_hi);
    cudaGetSymbolAddress((void**)&wql, g_wqkv_lo);
    cudaGetSymbolAddress((void**)&wph, g_wproj_hi);
    cudaGetSymbolAddress((void**)&wpl, g_wproj_lo);

    // 0) weight splits
    split_f16<<<(C3 * CIN + 255) / 256, 256>>>(w_qkv, wqh, wql, C3 * CIN);
    split_f16<<<(256 * CATT + 255) / 256, 256>>>(w_proj, wph, wpl, 256 * CATT);

    // 1) qkv GEMM (fp16 3-term split, fused x transpose): M=768, K=256
    {
        dim3 grid(HWN / 128, C3 / 128, BATCH);   // (32, 6, 16)
        gemm_qkv<<<grid, 256>>>(wqh, wql, x, qkv_s, C3, CIN);
    }

    // 2+3) fused depthwise 5x5 + grouped pointwise -> agg
    {
        dim3 grid(4, PWG, BATCH);                // (4, 96, 16)
        dwpw<<<grid, 256>>>(qkv_s, w_dw, w_pw, agg_s);
    }

    // 4) attention -> transposed fp16
    relu_lin_att<<<BATCH * 64, 256>>>(qkv_s, agg_s, att);

    // 5) proj GEMM (fp16 2-term split) + BN: M=256, K=512
    {
        dim3 grid(HWN / 128, 256 / 128, BATCH);  // (32, 2, 16)
        gemm_proj<<<grid, 256>>>(wph, wpl, att, out, 256, CATT,
                                 gamma, beta, mean, var);
    }
}

// round 15
// speedup vs baseline: 1.0033x; 1.0033x over previous
#include <cuda_runtime.h>
#include <cuda_fp16.h>
#include <cstdint>

// Problem constants
#define BATCH 16
#define CIN   256
#define HWN   4096          // 64*64
#define C3    768           // 3*TOTAL
#define CATT  512           // 2*TOTAL
#define PWG   96

// ---------------------------------------------------------------------------
// Scratch (static device memory)
// ---------------------------------------------------------------------------
__device__ float g_qkv[BATCH * C3 * HWN];               // 201 MB
__device__ float g_agg[BATCH * C3 * HWN];               // 201 MB
__device__ __half g_attT[BATCH * HWN * CATT];           // 67 MB (fp16, single)
__device__ __half g_wqkv_hi[C3 * CIN];
__device__ __half g_wqkv_lo[C3 * CIN];
__device__ __half g_wproj_hi[256 * CATT];
__device__ __half g_wproj_lo[256 * CATT];

// ---------------------------------------------------------------------------
// Helpers
// ---------------------------------------------------------------------------
__device__ __forceinline__ uint32_t smem_u32(const void* p) {
    uint32_t a;
    asm("{ .reg .u64 t; cvta.to.shared.u64 t, %1; cvt.u32.u64 %0, t; }" : "=r"(a) : "l"(p));
    return a;
}
__device__ __forceinline__ void ldmx4(uint32_t* r, uint32_t addr) {
    asm volatile("ldmatrix.sync.aligned.m8n8.x4.shared.b16 {%0,%1,%2,%3}, [%4];"
                 : "=r"(r[0]), "=r"(r[1]), "=r"(r[2]), "=r"(r[3]) : "r"(addr));
}
__device__ __forceinline__ void ldmx2(uint32_t* r, uint32_t addr) {
    asm volatile("ldmatrix.sync.aligned.m8n8.x2.shared.b16 {%0,%1}, [%2];"
                 : "=r"(r[0]), "=r"(r[1]) : "r"(addr));
}
__device__ __forceinline__ void mma_f16(float* d, const uint32_t* a, const uint32_t* b) {
    asm volatile(
        "mma.sync.aligned.m16n8k16.row.col.f32.f16.f16.f32 "
        "{%0,%1,%2,%3}, {%4,%5,%6,%7}, {%8,%9}, {%0,%1,%2,%3};"
        : "+f"(d[0]), "+f"(d[1]), "+f"(d[2]), "+f"(d[3])
        : "r"(a[0]), "r"(a[1]), "r"(a[2]), "r"(a[3]), "r"(b[0]), "r"(b[1]));
}

// ---------------------------------------------------------------------------
// fp16 weight split
// ---------------------------------------------------------------------------
__global__ void split_f16(const float* __restrict__ src,
                          __half* __restrict__ hi, __half* __restrict__ lo, int n) {
    int i = blockIdx.x * 256 + threadIdx.x;
    if (i < n) {
        float v = src[i];
        __half h = __float2half_rn(v);
        hi[i] = h;
        lo[i] = __float2half_rn(v - __half2float(h));
    }
}

// ---------------------------------------------------------------------------
// qkv GEMM: fp16 3-term split, fused x transpose+split in the B loader.
// ---------------------------------------------------------------------------
#define BK  32
#define LDS 40

__global__ __launch_bounds__(256, 2) void gemm_qkv(
    const __half* __restrict__ Ahi, const __half* __restrict__ Alo,
    const float* __restrict__ Xg, float* __restrict__ Cg, int M, int K) {
    __shared__ __half As_hi[128 * LDS];
    __shared__ __half As_lo[128 * LDS];
    __shared__ __half Bs_hi[128 * LDS];
    __shared__ __half Bs_lo[128 * LDS];

    const int tid = threadIdx.x;
    const int wid = tid >> 5;
    const int lane = tid & 31;

    const int b = blockIdx.z;
    const int m0 = blockIdx.y * 128;
    const int n0 = blockIdx.x * 128;

    const float* Xb = Xg + (size_t)b * CIN * HWN;

    const int wm = (wid >> 2) * 64;
    const int wn = (wid & 3) * 32;

    const int ar = lane & 15, ac = (lane >> 4) << 3;
    const int br = lane & 7,  bc = ((lane >> 3) & 1) << 3;

    const int pair = tid & 15;
    const int pgrp = tid >> 4;

    float acc[4][4][4];
#pragma unroll
    for (int mt = 0; mt < 4; mt++)
#pragma unroll
        for (int nt = 0; nt < 4; nt++)
#pragma unroll
            for (int r = 0; r < 4; r++) acc[mt][nt][r] = 0.f;

    for (int kc = 0; kc < K; kc += BK) {
#pragma unroll
        for (int i = 0; i < 2; i++) {
            int u = tid + 256 * i;
            int row = u >> 2;
            int cu = (u & 3) << 3;
            size_t sa = (size_t)(m0 + row) * K + kc + cu;
            *(uint4*)&As_hi[row * LDS + cu] = *(const uint4*)(Ahi + sa);
            *(uint4*)&As_lo[row * LDS + cu] = *(const uint4*)(Alo + sa);
        }
        {
            const float* x0 = Xb + (size_t)(kc + 2 * pair) * HWN + n0 + pgrp * 8;
            const float* x1 = x0 + HWN;
            float4 a0 = *(const float4*)(x0);
            float4 a1 = *(const float4*)(x0 + 4);
            float4 c0 = *(const float4*)(x1);
            float4 c1 = *(const float4*)(x1 + 4);
            float va[8] = {a0.x, a0.y, a0.z, a0.w, a1.x, a1.y, a1.z, a1.w};
            float vb[8] = {c0.x, c0.y, c0.z, c0.w, c1.x, c1.y, c1.z, c1.w};
#pragma unroll
            for (int i = 0; i < 8; i++) {
                __half h0 = __float2half_rn(va[i]);
                __half l0 = __float2half_rn(va[i] - __half2float(h0));
                __half h1 = __float2half_rn(vb[i]);
                __half l1 = __float2half_rn(vb[i] - __half2float(h1));
                int off = (pgrp * 8 + i) * LDS + 2 * pair;
                *(__half2*)&Bs_hi[off] = __halves2half2(h0, h1);
                *(__half2*)&Bs_lo[off] = __halves2half2(l0, l1);
            }
        }
        __syncthreads();

#pragma unroll
        for (int kk = 0; kk < BK; kk += 16) {
            uint32_t ah[4][4], bhf[4][2];
#pragma unroll
            for (int mt = 0; mt < 4; mt++)
                ldmx4(ah[mt], smem_u32(&As_hi[(wm + mt * 16 + ar) * LDS + kk + ac]));
#pragma unroll
            for (int nt = 0; nt < 4; nt++)
                ldmx2(bhf[nt], smem_u32(&Bs_hi[(wn + nt * 8 + br) * LDS + kk + bc]));
#pragma unroll
            for (int mt = 0; mt < 4; mt++)
#pragma unroll
                for (int nt = 0; nt < 4; nt++)
                    mma_f16(acc[mt][nt], ah[mt], bhf[nt]);

            uint32_t al[4][4];
#pragma unroll
            for (int mt = 0; mt < 4; mt++)
                ldmx4(al[mt], smem_u32(&As_lo[(wm + mt * 16 + ar) * LDS + kk + ac]));
#pragma unroll
            for (int mt = 0; mt < 4; mt++)
#pragma unroll
                for (int nt = 0; nt < 4; nt++)
                    mma_f16(acc[mt][nt], al[mt], bhf[nt]);

            uint32_t blf[4][2];
#pragma unroll
            for (int nt = 0; nt < 4; nt++)
                ldmx2(blf[nt], smem_u32(&Bs_lo[(wn + nt * 8 + br) * LDS + kk + bc]));
#pragma unroll
            for (int mt = 0; mt < 4; mt++)
#pragma unroll
                for (int nt = 0; nt < 4; nt++)
                    mma_f16(acc[mt][nt], ah[mt], blf[nt]);
        }
        __syncthreads();
    }

#pragma unroll
    for (int mt = 0; mt < 4; mt++) {
        const int row0 = m0 + wm + mt * 16 + (lane >> 2);
        const int row1 = row0 + 8;
        float* c0p = Cg + ((size_t)b * M + row0) * HWN + n0 + wn;
        float* c1p = Cg + ((size_t)b * M + row1) * HWN + n0 + wn;
        const int coff = ((lane & 3) << 1);
#pragma unroll
        for (int nt = 0; nt < 4; nt++) {
            *(float2*)(c0p + nt * 8 + coff) = make_float2(acc[mt][nt][0], acc[mt][nt][1]);
            *(float2*)(c1p + nt * 8 + coff) = make_float2(acc[mt][nt][2], acc[mt][nt][3]);
        }
    }
}

// ---------------------------------------------------------------------------
// proj GEMM: fp16 2-term split + BN epilogue (proven R13 version).
// ---------------------------------------------------------------------------
__global__ __launch_bounds__(256, 2) void gemm_proj(
    const __half* __restrict__ Ahi, const __half* __restrict__ Alo,
    const __half* __restrict__ Bg, float* __restrict__ Cg, int M, int K,
    const float* __restrict__ gamma, const float* __restrict__ beta,
    const float* __restrict__ mean, const float* __restrict__ var) {
    __shared__ __half As_hi[128 * LDS];
    __shared__ __half As_lo[128 * LDS];
    __shared__ __half Bs[128 * LDS];

    const int tid = threadIdx.x;
    const int wid = tid >> 5;
    const int lane = tid & 31;

    const int b = blockIdx.z;
    const int m0 = blockIdx.y * 128;
    const int n0 = blockIdx.x * 128;

    const __half* Bb = Bg + (size_t)b * HWN * K;

    const int wm = (wid >> 2) * 64;
    const int wn = (wid & 3) * 32;

    const int ar = lane & 15, ac = (lane >> 4) << 3;
    const int br = lane & 7,  bc = ((lane >> 3) & 1) << 3;

    float acc[4][4][4];
#pragma unroll
    for (int mt = 0; mt < 4; mt++)
#pragma unroll
        for (int nt = 0; nt < 4; nt++)
#pragma unroll
            for (int r = 0; r < 4; r++) acc[mt][nt][r] = 0.f;

    for (int kc = 0; kc < K; kc += BK) {
#pragma unroll
        for (int i = 0; i < 2; i++) {
            int u = tid + 256 * i;
            int row = u >> 2;
            int cu = (u & 3) << 3;
            size_t sa = (size_t)(m0 + row) * K + kc + cu;
            *(uint4*)&As_hi[row * LDS + cu] = *(const uint4*)(Ahi + sa);
            *(uint4*)&As_lo[row * LDS + cu] = *(const uint4*)(Alo + sa);
            size_t sb = (size_t)(n0 + row) * K + kc + cu;
            *(uint4*)&Bs[row * LDS + cu] = *(const uint4*)(Bb + sb);
        }
        __syncthreads();

#pragma unroll
        for (int kk = 0; kk < BK; kk += 16) {
            uint32_t ah[4][4], bf[4][2];
#pragma unroll
            for (int mt = 0; mt < 4; mt++)
                ldmx4(ah[mt], smem_u32(&As_hi[(wm + mt * 16 + ar) * LDS + kk + ac]));
#pragma unroll
            for (int nt = 0; nt < 4; nt++)
                ldmx2(bf[nt], smem_u32(&Bs[(wn + nt * 8 + br) * LDS + kk + bc]));
#pragma unroll
            for (int mt = 0; mt < 4; mt++)
#pragma unroll
                for (int nt = 0; nt < 4; nt++)
                    mma_f16(acc[mt][nt], ah[mt], bf[nt]);

            uint32_t al[4][4];
#pragma unroll
            for (int mt = 0; mt < 4; mt++)
                ldmx4(al[mt], smem_u32(&As_lo[(wm + mt * 16 + ar) * LDS + kk + ac]));
#pragma unroll
            for (int mt = 0; mt < 4; mt++)
#pragma unroll
                for (int nt = 0; nt < 4; nt++)
                    mma_f16(acc[mt][nt], al[mt], bf[nt]);
        }
        __syncthreads();
    }

#pragma unroll
    for (int mt = 0; mt < 4; mt++) {
        const int row0 = m0 + wm + mt * 16 + (lane >> 2);
        const int row1 = row0 + 8;
        float iv0 = gamma[row0] * rsqrtf(var[row0] + 1e-5f);
        float s0 = iv0, o0 = beta[row0] - mean[row0] * iv0;
        float iv1 = gamma[row1] * rsqrtf(var[row1] + 1e-5f);
        float s1 = iv1, o1 = beta[row1] - mean[row1] * iv1;
        float* c0p = Cg + ((size_t)b * M + row0) * HWN + n0 + wn;
        float* c1p = Cg + ((size_t)b * M + row1) * HWN + n0 + wn;
        const int coff = ((lane & 3) << 1);
#pragma unroll
        for (int nt = 0; nt < 4; nt++) {
            float2 v0, v1;
            v0.x = acc[mt][nt][0] * s0 + o0;
            v0.y = acc[mt][nt][1] * s0 + o0;
            v1.x = acc[mt][nt][2] * s1 + o1;
            v1.y = acc[mt][nt][3] * s1 + o1;
            *(float2*)(c0p + nt * 8 + coff) = v0;
            *(float2*)(c1p + nt * 8 + coff) = v1;
        }
    }
}

// ---------------------------------------------------------------------------
// FUSED depthwise 5x5 (pad 2) + grouped 1x1 (8-ch groups).
// R15: R13's proven scalar compute pattern, but 32x16 tile (halo 36x20):
// smem 24 KB -> 8 CTAs/SM (warp-limited, ~100% occ) vs 5 before.
// Thread = 1 column x 2-row strip. grid (8, 96, 16).
// ---------------------------------------------------------------------------
__global__ __launch_bounds__(256) void dwpw(
    const float* __restrict__ qkv, const float* __restrict__ w_dw,
    const float* __restrict__ w_pw, float* __restrict__ agg) {
    const int tile = blockIdx.x;           // 0..7
    const int g = blockIdx.y;              // 0..95
    const int b = blockIdx.z;
    const int tx = (tile & 1) * 32;
    const int ty = (tile >> 1) * 16;       // 0,16,32,48

    __shared__ float h[8][20 * 36];        // 20 halo rows x 36 cols
    __shared__ float wd[8][25];
    __shared__ float wp[64];

    const int tid = threadIdx.x;
    if (tid < 64) wp[tid] = w_pw[g * 64 + tid];
    if (tid < 200) {
        int c = tid / 25, t = tid % 25;
        wd[c][t] = w_dw[(g * 8 + c) * 25 + t];
    }

    const float* ip = qkv + ((size_t)b * C3 + (size_t)g * 8) * HWN;
    for (int idx = tid; idx < 8 * 720; idx += 256) {
        int c = idx / 720, rem = idx - c * 720;
        int hy = rem / 36, hx = rem - hy * 36;
        int gy = ty + hy - 2, gx = tx + hx - 2;
        float v = 0.f;
        if ((unsigned)gy < 64u && (unsigned)gx < 64u) v = ip[(size_t)c * HWN + gy * 64 + gx];
        h[c][rem] = v;
    }
    __syncthreads();

    const int lx = tid & 31;          // column
    const int sy = (tid >> 5) << 1;   // strip row base (0,2,...,14)

    float d[8][2];
#pragma unroll
    for (int c = 0; c < 8; c++) {
        float a0 = 0.f, a1 = 0.f;
#pragma unroll
        for (int r = 0; r < 6; r++) {
            const float* hp = &h[c][(sy + r) * 36 + lx];
            float v0 = hp[0], v1 = hp[1], v2 = hp[2], v3 = hp[3], v4 = hp[4];
#pragma unroll
            for (int j = 0; j < 2; j++) {
                int dy = r - j;
                if (dy >= 0 && dy < 5) {
                    float s = v0 * wd[c][dy * 5 + 0];
                    s = fmaf(v1, wd[c][dy * 5 + 1], s);
                    s = fmaf(v2, wd[c][dy * 5 + 2], s);
                    s = fmaf(v3, wd[c][dy * 5 + 3], s);
                    s = fmaf(v4, wd[c][dy * 5 + 4], s);
                    if (j == 0) a0 += s;
                    else a1 += s;
                }
            }
        }
        d[c][0] = a0; d[c][1] = a1;
    }

    float* op = agg + ((size_t)b * C3 + (size_t)g * 8) * HWN;
#pragma unroll
    for (int j = 0; j < 2; j++) {
        size_t pbase = (size_t)(ty + sy + j) * 64 + tx + lx;
#pragma unroll
        for (int o = 0; o < 8; o++) {
            float s = 0.f;
#pragma unroll
            for (int c = 0; c < 8; c++) s = fmaf(wp[o * 8 + c], d[c][j], s);
            op[(size_t)o * HWN + pbase] = s;
        }
    }
}

// ---------------------------------------------------------------------------
// ReLU linear attention; writes transposed fp16 output attT[b][n][g*8+e].
// ---------------------------------------------------------------------------
__global__ __launch_bounds__(256) void relu_lin_att(
    const float* __restrict__ qkv, const float* __restrict__ agg,
    __half* __restrict__ outp) {
    const int bg = blockIdx.x;
    const int b = bg >> 6;
    const int g = bg & 63;
    const float* base = (g < 32)
        ? qkv + ((size_t)b * C3 + (size_t)g * 24) * HWN
        : agg + ((size_t)b * C3 + (size_t)(g - 32) * 24) * HWN;

    __shared__ float kvs[72];
    const int tid = threadIdx.x;
    const int w = tid >> 5;
    const int lane = tid & 31;

    float kvr[9];
#pragma unroll
    for (int i = 0; i < 9; i++) kvr[i] = 0.f;

    const float* kch = base + (size_t)(8 + w) * HWN;
    for (int n4 = lane * 4; n4 < HWN; n4 += 128) {
        float4 kk = *(const float4*)(kch + n4);
        kk.x = fmaxf(kk.x, 0.f); kk.y = fmaxf(kk.y, 0.f);
        kk.z = fmaxf(kk.z, 0.f); kk.w = fmaxf(kk.w, 0.f);
#pragma unroll
        for (int e = 0; e < 8; e++) {
            float4 vv = *(const float4*)(base + (size_t)(16 + e) * HWN + n4);
            kvr[e] = fmaf(kk.x, vv.x, kvr[e]);
            kvr[e] = fmaf(kk.y, vv.y, kvr[e]);
            kvr[e] = fmaf(kk.z, vv.z, kvr[e]);
            kvr[e] = fmaf(kk.w, vv.w, kvr[e]);
        }
        kvr[8] += kk.x + kk.y + kk.z + kk.w;
    }
#pragma unroll
    for (int i = 0; i < 9; i++) {
        float v = kvr[i];
        v += __shfl_xor_sync(0xffffffffu, v, 16);
        v += __shfl_xor_sync(0xffffffffu, v, 8);
        v += __shfl_xor_sync(0xffffffffu, v, 4);
        v += __shfl_xor_sync(0xffffffffu, v, 2);
        v += __shfl_xor_sync(0xffffffffu, v, 1);
        if (lane == 0) kvs[w * 9 + i] = v;
    }
    __syncthreads();

    for (int n4 = tid * 4; n4 < HWN; n4 += 1024) {
        float4 q4[8];
#pragma unroll
        for (int d0 = 0; d0 < 8; d0++) {
            float4 q = *(const float4*)(base + (size_t)d0 * HWN + n4);
            q.x = fmaxf(q.x, 0.f); q.y = fmaxf(q.y, 0.f);
            q.z = fmaxf(q.z, 0.f); q.w = fmaxf(q.w, 0.f);
            q4[d0] = q;
        }
#pragma unroll
        for (int px = 0; px < 4; px++) {
            float qd[8];
#pragma unroll
            for (int d0 = 0; d0 < 8; d0++)
                qd[d0] = px == 0 ? q4[d0].x : px == 1 ? q4[d0].y : px == 2 ? q4[d0].z : q4[d0].w;
            float den = 0.f;
#pragma unroll
            for (int d0 = 0; d0 < 8; d0++) den = fmaf(qd[d0], kvs[d0 * 9 + 8], den);
            float rden = 1.f / (den + 1e-15f);
            __align__(16) __half o[8];
#pragma unroll
            for (int e = 0; e < 8; e++) {
                float num = 0.f;
#pragma unroll
                for (int d0 = 0; d0 < 8; d0++) num = fmaf(qd[d0], kvs[d0 * 9 + e], num);
                o[e] = __float2half_rn(num * rden);
            }
            size_t idx = ((size_t)b * HWN + n4 + px) * CATT + g * 8;
            *(uint4*)(outp + idx) = *(const uint4*)o;
        }
    }
}

// ---------------------------------------------------------------------------
// Launch
// ---------------------------------------------------------------------------
extern "C" void kernel_launch(void* const* d_in, const int* in_sizes, int n_in,
                              void* d_out, int out_size) {
    const float* x      = (const float*)d_in[0];
    const float* w_qkv  = (const float*)d_in[1];
    const float* w_dw   = (const float*)d_in[2];
    const float* w_pw   = (const float*)d_in[3];
    const float* w_proj = (const float*)d_in[4];
    const float* gamma  = (const float*)d_in[5];
    const float* beta   = (const float*)d_in[6];
    const float* mean   = (const float*)d_in[7];
    const float* var    = (const float*)d_in[8];
    float* out = (float*)d_out;

    float *qkv_s, *agg_s;
    __half *att, *wqh, *wql, *wph, *wpl;
    cudaGetSymbolAddress((void**)&qkv_s, g_qkv);
    cudaGetSymbolAddress((void**)&agg_s, g_agg);
    cudaGetSymbolAddress((void**)&att, g_attT);
    cudaGetSymbolAddress((void**)&wqh, g_wqkv_hi);
    cudaGetSymbolAddress((void**)&wql, g_wqkv_lo);
    cudaGetSymbolAddress((void**)&wph, g_wproj_hi);
    cudaGetSymbolAddress((void**)&wpl, g_wproj_lo);

    // 0) weight splits
    split_f16<<<(C3 * CIN + 255) / 256, 256>>>(w_qkv, wqh, wql, C3 * CIN);
    split_f16<<<(256 * CATT + 255) / 256, 256>>>(w_proj, wph, wpl, 256 * CATT);

    // 1) qkv GEMM (fp16 3-term split, fused x transpose): M=768, K=256
    {
        dim3 grid(HWN / 128, C3 / 128, BATCH);   // (32, 6, 16)
        gemm_qkv<<<grid, 256>>>(wqh, wql, x, qkv_s, C3, CIN);
    }

    // 2+3) fused depthwise 5x5 + grouped pointwise -> agg (32x16 tiles)
    {
        dim3 grid(8, PWG, BATCH);                // (8, 96, 16)
        dwpw<<<grid, 256>>>(qkv_s, w_dw, w_pw, agg_s);
    }

    // 4) attention -> transposed fp16
    relu_lin_att<<<BATCH * 64, 256>>>(qkv_s, agg_s, att);

    // 5) proj GEMM (fp16 2-term split) + BN: M=256, K=512
    {
        dim3 grid(HWN / 128, 256 / 128, BATCH);  // (32, 2, 16)
        gemm_proj<<<grid, 256>>>(wph, wpl, att, out, 256, CATT,
                                 gamma, beta, mean, var);
    }
}

// round 16
// speedup vs baseline: 1.0681x; 1.0646x over previous
#include <cuda_runtime.h>
#include <cuda_fp16.h>
#include <cstdint>

// Problem constants
#define BATCH 16
#define CIN   256
#define HWN   4096          // 64*64
#define C3    768           // 3*TOTAL
#define CATT  512           // 2*TOTAL
#define PWG   96

// ---------------------------------------------------------------------------
// Scratch (static device memory)
// ---------------------------------------------------------------------------
__device__ float g_qkv[BATCH * C3 * HWN];               // 201 MB
__device__ float g_agg[BATCH * C3 * HWN];               // 201 MB
__device__ __half g_attT[BATCH * HWN * CATT];           // 67 MB
__device__ __half g_wqkv_hi[C3 * CIN];
__device__ __half g_wqkv_lo[C3 * CIN];
__device__ __half g_wproj_hi[256 * CATT];
__device__ __half g_wproj_lo[256 * CATT];

// ---------------------------------------------------------------------------
// Helpers
// ---------------------------------------------------------------------------
__device__ __forceinline__ uint32_t smem_u32(const void* p) {
    uint32_t a;
    asm("{ .reg .u64 t; cvta.to.shared.u64 t, %1; cvt.u32.u64 %0, t; }" : "=r"(a) : "l"(p));
    return a;
}
__device__ __forceinline__ void ldmx4(uint32_t* r, uint32_t addr) {
    asm volatile("ldmatrix.sync.aligned.m8n8.x4.shared.b16 {%0,%1,%2,%3}, [%4];"
                 : "=r"(r[0]), "=r"(r[1]), "=r"(r[2]), "=r"(r[3]) : "r"(addr));
}
__device__ __forceinline__ void ldmx2(uint32_t* r, uint32_t addr) {
    asm volatile("ldmatrix.sync.aligned.m8n8.x2.shared.b16 {%0,%1}, [%2];"
                 : "=r"(r[0]), "=r"(r[1]) : "r"(addr));
}
__device__ __forceinline__ void mma_f16(float* d, const uint32_t* a, const uint32_t* b) {
    asm volatile(
        "mma.sync.aligned.m16n8k16.row.col.f32.f16.f16.f32 "
        "{%0,%1,%2,%3}, {%4,%5,%6,%7}, {%8,%9}, {%0,%1,%2,%3};"
        : "+f"(d[0]), "+f"(d[1]), "+f"(d[2]), "+f"(d[3])
        : "r"(a[0]), "r"(a[1]), "r"(a[2]), "r"(a[3]), "r"(b[0]), "r"(b[1]));
}

// ---------------------------------------------------------------------------
// fp16 weight split
// ---------------------------------------------------------------------------
__global__ void split_f16(const float* __restrict__ src,
                          __half* __restrict__ hi, __half* __restrict__ lo, int n) {
    int i = blockIdx.x * 256 + threadIdx.x;
    if (i < n) {
        float v = src[i];
        __half h = __float2half_rn(v);
        hi[i] = h;
        lo[i] = __float2half_rn(v - __half2float(h));
    }
}

// ---------------------------------------------------------------------------
// qkv GEMM: fp16 3-term split, fused x transpose+split in the B loader.
// ---------------------------------------------------------------------------
#define BK  32
#define LDS 40

__global__ __launch_bounds__(256, 2) void gemm_qkv(
    const __half* __restrict__ Ahi, const __half* __restrict__ Alo,
    const float* __restrict__ Xg, float* __restrict__ Cg, int M, int K) {
    __shared__ __half As_hi[128 * LDS];
    __shared__ __half As_lo[128 * LDS];
    __shared__ __half Bs_hi[128 * LDS];
    __shared__ __half Bs_lo[128 * LDS];

    const int tid = threadIdx.x;
    const int wid = tid >> 5;
    const int lane = tid & 31;

    const int b = blockIdx.z;
    const int m0 = blockIdx.y * 128;
    const int n0 = blockIdx.x * 128;

    const float* Xb = Xg + (size_t)b * CIN * HWN;

    const int wm = (wid >> 2) * 64;
    const int wn = (wid & 3) * 32;

    const int ar = lane & 15, ac = (lane >> 4) << 3;
    const int br = lane & 7,  bc = ((lane >> 3) & 1) << 3;

    const int pair = tid & 15;
    const int pgrp = tid >> 4;

    float acc[4][4][4];
#pragma unroll
    for (int mt = 0; mt < 4; mt++)
#pragma unroll
        for (int nt = 0; nt < 4; nt++)
#pragma unroll
            for (int r = 0; r < 4; r++) acc[mt][nt][r] = 0.f;

    for (int kc = 0; kc < K; kc += BK) {
#pragma unroll
        for (int i = 0; i < 2; i++) {
            int u = tid + 256 * i;
            int row = u >> 2;
            int cu = (u & 3) << 3;
            size_t sa = (size_t)(m0 + row) * K + kc + cu;
            *(uint4*)&As_hi[row * LDS + cu] = *(const uint4*)(Ahi + sa);
            *(uint4*)&As_lo[row * LDS + cu] = *(const uint4*)(Alo + sa);
        }
        {
            const float* x0 = Xb + (size_t)(kc + 2 * pair) * HWN + n0 + pgrp * 8;
            const float* x1 = x0 + HWN;
            float4 a0 = *(const float4*)(x0);
            float4 a1 = *(const float4*)(x0 + 4);
            float4 c0 = *(const float4*)(x1);
            float4 c1 = *(const float4*)(x1 + 4);
            float va[8] = {a0.x, a0.y, a0.z, a0.w, a1.x, a1.y, a1.z, a1.w};
            float vb[8] = {c0.x, c0.y, c0.z, c0.w, c1.x, c1.y, c1.z, c1.w};
#pragma unroll
            for (int i = 0; i < 8; i++) {
                __half h0 = __float2half_rn(va[i]);
                __half l0 = __float2half_rn(va[i] - __half2float(h0));
                __half h1 = __float2half_rn(vb[i]);
                __half l1 = __float2half_rn(vb[i] - __half2float(h1));
                int off = (pgrp * 8 + i) * LDS + 2 * pair;
                *(__half2*)&Bs_hi[off] = __halves2half2(h0, h1);
                *(__half2*)&Bs_lo[off] = __halves2half2(l0, l1);
            }
        }
        __syncthreads();

#pragma unroll
        for (int kk = 0; kk < BK; kk += 16) {
            uint32_t ah[4][4], bhf[4][2];
#pragma unroll
            for (int mt = 0; mt < 4; mt++)
                ldmx4(ah[mt], smem_u32(&As_hi[(wm + mt * 16 + ar) * LDS + kk + ac]));
#pragma unroll
            for (int nt = 0; nt < 4; nt++)
                ldmx2(bhf[nt], smem_u32(&Bs_hi[(wn + nt * 8 + br) * LDS + kk + bc]));
#pragma unroll
            for (int mt = 0; mt < 4; mt++)
#pragma unroll
                for (int nt = 0; nt < 4; nt++)
                    mma_f16(acc[mt][nt], ah[mt], bhf[nt]);

            uint32_t al[4][4];
#pragma unroll
            for (int mt = 0; mt < 4; mt++)
                ldmx4(al[mt], smem_u32(&As_lo[(wm + mt * 16 + ar) * LDS + kk + ac]));
#pragma unroll
            for (int mt = 0; mt < 4; mt++)
#pragma unroll
                for (int nt = 0; nt < 4; nt++)
                    mma_f16(acc[mt][nt], al[mt], bhf[nt]);

            uint32_t blf[4][2];
#pragma unroll
            for (int nt = 0; nt < 4; nt++)
                ldmx2(blf[nt], smem_u32(&Bs_lo[(wn + nt * 8 + br) * LDS + kk + bc]));
#pragma unroll
            for (int mt = 0; mt < 4; mt++)
#pragma unroll
                for (int nt = 0; nt < 4; nt++)
                    mma_f16(acc[mt][nt], ah[mt], blf[nt]);
        }
        __syncthreads();
    }

#pragma unroll
    for (int mt = 0; mt < 4; mt++) {
        const int row0 = m0 + wm + mt * 16 + (lane >> 2);
        const int row1 = row0 + 8;
        float* c0p = Cg + ((size_t)b * M + row0) * HWN + n0 + wn;
        float* c1p = Cg + ((size_t)b * M + row1) * HWN + n0 + wn;
        const int coff = ((lane & 3) << 1);
#pragma unroll
        for (int nt = 0; nt < 4; nt++) {
            *(float2*)(c0p + nt * 8 + coff) = make_float2(acc[mt][nt][0], acc[mt][nt][1]);
            *(float2*)(c1p + nt * 8 + coff) = make_float2(acc[mt][nt][2], acc[mt][nt][3]);
        }
    }
}

// ---------------------------------------------------------------------------
// proj GEMM: fp16 2-term split + BN epilogue.
// ---------------------------------------------------------------------------
__global__ __launch_bounds__(256, 2) void gemm_proj(
    const __half* __restrict__ Ahi, const __half* __restrict__ Alo,
    const __half* __restrict__ Bg, float* __restrict__ Cg, int M, int K,
    const float* __restrict__ gamma, const float* __restrict__ beta,
    const float* __restrict__ mean, const float* __restrict__ var) {
    __shared__ __half As_hi[128 * LDS];
    __shared__ __half As_lo[128 * LDS];
    __shared__ __half Bs[128 * LDS];

    const int tid = threadIdx.x;
    const int wid = tid >> 5;
    const int lane = tid & 31;

    const int b = blockIdx.z;
    const int m0 = blockIdx.y * 128;
    const int n0 = blockIdx.x * 128;

    const __half* Bb = Bg + (size_t)b * HWN * K;

    const int wm = (wid >> 2) * 64;
    const int wn = (wid & 3) * 32;

    const int ar = lane & 15, ac = (lane >> 4) << 3;
    const int br = lane & 7,  bc = ((lane >> 3) & 1) << 3;

    float acc[4][4][4];
#pragma unroll
    for (int mt = 0; mt < 4; mt++)
#pragma unroll
        for (int nt = 0; nt < 4; nt++)
#pragma unroll
            for (int r = 0; r < 4; r++) acc[mt][nt][r] = 0.f;

    for (int kc = 0; kc < K; kc += BK) {
#pragma unroll
        for (int i = 0; i < 2; i++) {
            int u = tid + 256 * i;
            int row = u >> 2;
            int cu = (u & 3) << 3;
            size_t sa = (size_t)(m0 + row) * K + kc + cu;
            *(uint4*)&As_hi[row * LDS + cu] = *(const uint4*)(Ahi + sa);
            *(uint4*)&As_lo[row * LDS + cu] = *(const uint4*)(Alo + sa);
            size_t sb = (size_t)(n0 + row) * K + kc + cu;
            *(uint4*)&Bs[row * LDS + cu] = *(const uint4*)(Bb + sb);
        }
        __syncthreads();

#pragma unroll
        for (int kk = 0; kk < BK; kk += 16) {
            uint32_t ah[4][4], bf[4][2];
#pragma unroll
            for (int mt = 0; mt < 4; mt++)
                ldmx4(ah[mt], smem_u32(&As_hi[(wm + mt * 16 + ar) * LDS + kk + ac]));
#pragma unroll
            for (int nt = 0; nt < 4; nt++)
                ldmx2(bf[nt], smem_u32(&Bs[(wn + nt * 8 + br) * LDS + kk + bc]));
#pragma unroll
            for (int mt = 0; mt < 4; mt++)
#pragma unroll
                for (int nt = 0; nt < 4; nt++)
                    mma_f16(acc[mt][nt], ah[mt], bf[nt]);

            uint32_t al[4][4];
#pragma unroll
            for (int mt = 0; mt < 4; mt++)
                ldmx4(al[mt], smem_u32(&As_lo[(wm + mt * 16 + ar) * LDS + kk + ac]));
#pragma unroll
            for (int mt = 0; mt < 4; mt++)
#pragma unroll
                for (int nt = 0; nt < 4; nt++)
                    mma_f16(acc[mt][nt], al[mt], bf[nt]);
        }
        __syncthreads();
    }

#pragma unroll
    for (int mt = 0; mt < 4; mt++) {
        const int row0 = m0 + wm + mt * 16 + (lane >> 2);
        const int row1 = row0 + 8;
        float iv0 = gamma[row0] * rsqrtf(var[row0] + 1e-5f);
        float s0 = iv0, o0 = beta[row0] - mean[row0] * iv0;
        float iv1 = gamma[row1] * rsqrtf(var[row1] + 1e-5f);
        float s1 = iv1, o1 = beta[row1] - mean[row1] * iv1;
        float* c0p = Cg + ((size_t)b * M + row0) * HWN + n0 + wn;
        float* c1p = Cg + ((size_t)b * M + row1) * HWN + n0 + wn;
        const int coff = ((lane & 3) << 1);
#pragma unroll
        for (int nt = 0; nt < 4; nt++) {
            float2 v0, v1;
            v0.x = acc[mt][nt][0] * s0 + o0;
            v0.y = acc[mt][nt][1] * s0 + o0;
            v1.x = acc[mt][nt][2] * s1 + o1;
            v1.y = acc[mt][nt][3] * s1 + o1;
            *(float2*)(c0p + nt * 8 + coff) = v0;
            *(float2*)(c1p + nt * 8 + coff) = v1;
        }
    }
}

// ---------------------------------------------------------------------------
// FUSED depthwise 5x5 + grouped 1x1 — exact R13 version (proven 171us).
// Block = (tile 32x32, group g, batch b). Thread = 1 column x 4-row strip.
// ---------------------------------------------------------------------------
__global__ __launch_bounds__(256) void dwpw(
    const float* __restrict__ qkv, const float* __restrict__ w_dw,
    const float* __restrict__ w_pw, float* __restrict__ agg) {
    const int tile = blockIdx.x;
    const int g = blockIdx.y;
    const int b = blockIdx.z;
    const int ty = (tile >> 1) * 32;
    const int tx = (tile & 1) * 32;

    __shared__ float h[8][36 * 36];
    __shared__ float wd[8][25];
    __shared__ float wp[64];

    const int tid = threadIdx.x;
    if (tid < 64) wp[tid] = w_pw[g * 64 + tid];
    if (tid < 200) {
        int c = tid / 25, t = tid % 25;
        wd[c][t] = w_dw[(g * 8 + c) * 25 + t];
    }

    const float* ip = qkv + ((size_t)b * C3 + (size_t)g * 8) * HWN;
    for (int idx = tid; idx < 8 * 1296; idx += 256) {
        int c = idx / 1296, rem = idx - c * 1296;
        int hy = rem / 36, hx = rem - hy * 36;
        int gy = ty + hy - 2, gx = tx + hx - 2;
        float v = 0.f;
        if ((unsigned)gy < 64u && (unsigned)gx < 64u) v = ip[(size_t)c * HWN + gy * 64 + gx];
        h[c][rem] = v;
    }
    __syncthreads();

    const int lx = tid & 31;
    const int sy = (tid >> 5) << 2;

    float d[8][4];
#pragma unroll
    for (int c = 0; c < 8; c++) {
        float a0 = 0.f, a1 = 0.f, a2 = 0.f, a3 = 0.f;
#pragma unroll
        for (int r = 0; r < 8; r++) {
            const float* hp = &h[c][(sy + r) * 36 + lx];
            float v0 = hp[0], v1 = hp[1], v2 = hp[2], v3 = hp[3], v4 = hp[4];
#pragma unroll
            for (int j = 0; j < 4; j++) {
                int dy = r - j;
                if (dy >= 0 && dy < 5) {
                    float s = v0 * wd[c][dy * 5 + 0];
                    s = fmaf(v1, wd[c][dy * 5 + 1], s);
                    s = fmaf(v2, wd[c][dy * 5 + 2], s);
                    s = fmaf(v3, wd[c][dy * 5 + 3], s);
                    s = fmaf(v4, wd[c][dy * 5 + 4], s);
                    if (j == 0) a0 += s;
                    else if (j == 1) a1 += s;
                    else if (j == 2) a2 += s;
                    else a3 += s;
                }
            }
        }
        d[c][0] = a0; d[c][1] = a1; d[c][2] = a2; d[c][3] = a3;
    }

    float* op = agg + ((size_t)b * C3 + (size_t)g * 8) * HWN;
#pragma unroll
    for (int j = 0; j < 4; j++) {
        size_t pbase = (size_t)(ty + sy + j) * 64 + tx + lx;
#pragma unroll
        for (int o = 0; o < 8; o++) {
            float s = 0.f;
#pragma unroll
            for (int c = 0; c < 8; c++) s = fmaf(wp[o * 8 + c], d[c][j], s);
            op[(size_t)o * HWN + pbase] = s;
        }
    }
}

// ---------------------------------------------------------------------------
// ReLU linear attention; writes transposed fp16 output attT[b][n][g*8+e].
// ---------------------------------------------------------------------------
__global__ __launch_bounds__(256) void relu_lin_att(
    const float* __restrict__ qkv, const float* __restrict__ agg,
    __half* __restrict__ outp) {
    const int bg = blockIdx.x;
    const int b = bg >> 6;
    const int g = bg & 63;
    const float* base = (g < 32)
        ? qkv + ((size_t)b * C3 + (size_t)g * 24) * HWN
        : agg + ((size_t)b * C3 + (size_t)(g - 32) * 24) * HWN;

    __shared__ float kvs[72];
    const int tid = threadIdx.x;
    const int w = tid >> 5;
    const int lane = tid & 31;

    float kvr[9];
#pragma unroll
    for (int i = 0; i < 9; i++) kvr[i] = 0.f;

    const float* kch = base + (size_t)(8 + w) * HWN;
    for (int n4 = lane * 4; n4 < HWN; n4 += 128) {
        float4 kk = *(const float4*)(kch + n4);
        kk.x = fmaxf(kk.x, 0.f); kk.y = fmaxf(kk.y, 0.f);
        kk.z = fmaxf(kk.z, 0.f); kk.w = fmaxf(kk.w, 0.f);
#pragma unroll
        for (int e = 0; e < 8; e++) {
            float4 vv = *(const float4*)(base + (size_t)(16 + e) * HWN + n4);
            kvr[e] = fmaf(kk.x, vv.x, kvr[e]);
            kvr[e] = fmaf(kk.y, vv.y, kvr[e]);
            kvr[e] = fmaf(kk.z, vv.z, kvr[e]);
            kvr[e] = fmaf(kk.w, vv.w, kvr[e]);
        }
        kvr[8] += kk.x + kk.y + kk.z + kk.w;
    }
#pragma unroll
    for (int i = 0; i < 9; i++) {
        float v = kvr[i];
        v += __shfl_xor_sync(0xffffffffu, v, 16);
        v += __shfl_xor_sync(0xffffffffu, v, 8);
        v += __shfl_xor_sync(0xffffffffu, v, 4);
        v += __shfl_xor_sync(0xffffffffu, v, 2);
        v += __shfl_xor_sync(0xffffffffu, v, 1);
        if (lane == 0) kvs[w * 9 + i] = v;
    }
    __syncthreads();

    for (int n4 = tid * 4; n4 < HWN; n4 += 1024) {
        float4 q4[8];
#pragma unroll
        for (int d0 = 0; d0 < 8; d0++) {
            float4 q = *(const float4*)(base + (size_t)d0 * HWN + n4);
            q.x = fmaxf(q.x, 0.f); q.y = fmaxf(q.y, 0.f);
            q.z = fmaxf(q.z, 0.f); q.w = fmaxf(q.w, 0.f);
            q4[d0] = q;
        }
#pragma unroll
        for (int px = 0; px < 4; px++) {
            float qd[8];
#pragma unroll
            for (int d0 = 0; d0 < 8; d0++)
                qd[d0] = px == 0 ? q4[d0].x : px == 1 ? q4[d0].y : px == 2 ? q4[d0].z : q4[d0].w;
            float den = 0.f;
#pragma unroll
            for (int d0 = 0; d0 < 8; d0++) den = fmaf(qd[d0], kvs[d0 * 9 + 8], den);
            float rden = 1.f / (den + 1e-15f);
            __align__(16) __half o[8];
#pragma unroll
            for (int e = 0; e < 8; e++) {
                float num = 0.f;
#pragma unroll
                for (int d0 = 0; d0 < 8; d0++) num = fmaf(qd[d0], kvs[d0 * 9 + e], num);
                o[e] = __float2half_rn(num * rden);
            }
            size_t idx = ((size_t)b * HWN + n4 + px) * CATT + g * 8;
            *(uint4*)(outp + idx) = *(const uint4*)o;
        }
    }
}

// ---------------------------------------------------------------------------
// Launch: 2-stream batch pipeline (batches 0-7 on stream 0, 8-15 on s1).
// ---------------------------------------------------------------------------
static void run_chain(cudaStream_t st, int b0,
                      const float* x, const float* w_dw, const float* w_pw,
                      const float* gamma, const float* beta,
                      const float* mean, const float* var,
                      float* qkv_s, float* agg_s, __half* att,
                      const __half* wqh, const __half* wql,
                      const __half* wph, const __half* wpl, float* out) {
    const int NB = BATCH / 2;
    const float* xb = x + (size_t)b0 * CIN * HWN;
    float* qkvb = qkv_s + (size_t)b0 * C3 * HWN;
    float* aggb = agg_s + (size_t)b0 * C3 * HWN;
    __half* attb = att + (size_t)b0 * HWN * CATT;
    float* outb = out + (size_t)b0 * 256 * HWN;

    {
        dim3 grid(HWN / 128, C3 / 128, NB);
        gemm_qkv<<<grid, 256, 0, st>>>(wqh, wql, xb, qkvb, C3, CIN);
    }
    {
        dim3 grid(4, PWG, NB);
        dwpw<<<grid, 256, 0, st>>>(qkvb, w_dw, w_pw, aggb);
    }
    relu_lin_att<<<NB * 64, 256, 0, st>>>(qkvb, aggb, attb);
    {
        dim3 grid(HWN / 128, 256 / 128, NB);
        gemm_proj<<<grid, 256, 0, st>>>(wph, wpl, attb, outb, 256, CATT,
                                        gamma, beta, mean, var);
    }
}

extern "C" void kernel_launch(void* const* d_in, const int* in_sizes, int n_in,
                              void* d_out, int out_size) {
    const float* x      = (const float*)d_in[0];
    const float* w_qkv  = (const float*)d_in[1];
    const float* w_dw   = (const float*)d_in[2];
    const float* w_pw   = (const float*)d_in[3];
    const float* w_proj = (const float*)d_in[4];
    const float* gamma  = (const float*)d_in[5];
    const float* beta   = (const float*)d_in[6];
    const float* mean   = (const float*)d_in[7];
    const float* var    = (const float*)d_in[8];
    float* out = (float*)d_out;

    float *qkv_s, *agg_s;
    __half *att, *wqh, *wql, *wph, *wpl;
    cudaGetSymbolAddress((void**)&qkv_s, g_qkv);
    cudaGetSymbolAddress((void**)&agg_s, g_agg);
    cudaGetSymbolAddress((void**)&att, g_attT);
    cudaGetSymbolAddress((void**)&wqh, g_wqkv_hi);
    cudaGetSymbolAddress((void**)&wql, g_wqkv_lo);
    cudaGetSymbolAddress((void**)&wph, g_wproj_hi);
    cudaGetSymbolAddress((void**)&wpl, g_wproj_lo);

    static cudaStream_t s1 = nullptr;
    static cudaEvent_t ev_fork = nullptr, ev_join = nullptr;
    if (!s1) {
        cudaStreamCreateWithFlags(&s1, cudaStreamNonBlocking);
        cudaEventCreateWithFlags(&ev_fork, cudaEventDisableTiming);
        cudaEventCreateWithFlags(&ev_join, cudaEventDisableTiming);
    }

    // 0) weight splits (both chains depend on these) — stream 0
    split_f16<<<(C3 * CIN + 255) / 256, 256>>>(w_qkv, wqh, wql, C3 * CIN);
    split_f16<<<(256 * CATT + 255) / 256, 256>>>(w_proj, wph, wpl, 256 * CATT);

    // fork
    cudaEventRecord(ev_fork, 0);
    cudaStreamWaitEvent(s1, ev_fork, 0);

    // chain A (batches 0-7) on stream 0; chain B (batches 8-15) on s1
    run_chain(0,  0, x, w_dw, w_pw, gamma, beta, mean, var,
              qkv_s, agg_s, att, wqh, wql, wph, wpl, out);
    run_chain(s1, 8, x, w_dw, w_pw, gamma, beta, mean, var,
              qkv_s, agg_s, att, wqh, wql, wph, wpl, out);

    // join
    cudaEventRecord(ev_join, s1);
    cudaStreamWaitEvent(0, ev_join, 0);
}